// round 15
// baseline (speedup 1.0000x reference)
#include <cuda_runtime.h>
#include <cuda_fp16.h>
#include <cstdint>

// Problem dims (fixed)
#define Dm   256
#define Bsz  4
#define Sq   512
#define HWk  4096
#define NH   8
#define HD   32
#define NSPLIT 4

// Scratch (no cudaMalloc allowed)
__device__ __half g_KVh[Bsz * Dm * HWk];          // kv half [b][k][m]
__device__ __half g_Qih[Bsz * Sq * Dm];           // query half
__device__ __half g_Wh[4 * Dm * Dm];              // Wq,Wk,Wv,Wo half
__device__ __half g_Qh[Bsz * Sq * Dm];            // projected Q (half, pre-scaled)
__device__ __half g_K [Bsz * HWk * Dm];           // projected K [b][hw][d]
__device__ __half g_Vt[Bsz * Dm * HWk];           // projected V transposed [b][d][hw]
__device__ __half g_Ah[Bsz * Sq * Dm];            // combined attention output (half)
__device__ float  g_Po[Bsz * NH * NSPLIT * Sq * HD];
__device__ float  g_Pm[Bsz * NH * NSPLIT * Sq];
__device__ float  g_Pl[Bsz * NH * NSPLIT * Sq];

__device__ __forceinline__ uint32_t f2h2(float x, float y) {
    __half2 h = __floats2half2_rn(x, y);
    return *reinterpret_cast<uint32_t*>(&h);
}
__device__ __forceinline__ float ex2f(float x) {
    float r;
    asm("ex2.approx.f32 %0, %1;" : "=f"(r) : "f"(x));
    return r;
}
__device__ __forceinline__ void mma_f16(float c[4], const uint32_t a[4],
                                        uint32_t b0, uint32_t b1) {
    asm volatile(
        "mma.sync.aligned.m16n8k16.row.col.f32.f16.f16.f32 "
        "{%0,%1,%2,%3}, {%4,%5,%6,%7}, {%8,%9}, {%0,%1,%2,%3};"
        : "+f"(c[0]), "+f"(c[1]), "+f"(c[2]), "+f"(c[3])
        : "r"(a[0]), "r"(a[1]), "r"(a[2]), "r"(a[3]), "r"(b0), "r"(b1));
}
__device__ __forceinline__ void ldsm_x4(uint32_t r[4], uint32_t addr) {
    asm volatile(
        "ldmatrix.sync.aligned.m8n8.x4.shared.b16 {%0,%1,%2,%3}, [%4];"
        : "=r"(r[0]), "=r"(r[1]), "=r"(r[2]), "=r"(r[3]) : "r"(addr));
}
__device__ __forceinline__ void ldsm_x4_t(uint32_t r[4], uint32_t addr) {
    asm volatile(
        "ldmatrix.sync.aligned.m8n8.x4.trans.shared.b16 {%0,%1,%2,%3}, [%4];"
        : "=r"(r[0]), "=r"(r[1]), "=r"(r[2]), "=r"(r[3]) : "r"(addr));
}
__device__ __forceinline__ uint32_t cvta_s(const void* p) {
    return (uint32_t)__cvta_generic_to_shared(p);
}
__device__ __forceinline__ void cp16(uint32_t dst, const void* src) {
    asm volatile("cp.async.cg.shared.global [%0], [%1], 16;"
                 :: "r"(dst), "l"(src));
}
__device__ __forceinline__ void cp_commit() {
    asm volatile("cp.async.commit_group;");
}
__device__ __forceinline__ void cp_wait0() {
    asm volatile("cp.async.wait_group 0;");
}

#define KS2 20    // [row][k2] half2 tiles
#define ATW 68    // proj KV A tile [k][m]
#define AQW 20    // proj Q A tile [m][k2]
#define VS2 36    // attn V [d][key] tile

// ---------------------------------------------------------------------------
// prep: fp32 -> fp16 conversions
// ---------------------------------------------------------------------------
__global__ void prep_half(const float* __restrict__ kv,
                          const float* __restrict__ query,
                          const float* __restrict__ Wq, const float* __restrict__ Wk,
                          const float* __restrict__ Wv, const float* __restrict__ Wo)
{
    const int idx = blockIdx.x * blockDim.x + threadIdx.x;
    const int stride = gridDim.x * blockDim.x;

    const int N1 = Bsz * Dm * HWk / 4;
    uint2* kvh = (uint2*)g_KVh;
    for (int i = idx; i < N1; i += stride) {
        float4 v = ((const float4*)kv)[i];
        kvh[i] = make_uint2(f2h2(v.x, v.y), f2h2(v.z, v.w));
    }
    const int N2 = Bsz * Sq * Dm / 4;
    uint2* qh = (uint2*)g_Qih;
    for (int i = idx; i < N2; i += stride) {
        float4 v = ((const float4*)query)[i];
        qh[i] = make_uint2(f2h2(v.x, v.y), f2h2(v.z, v.w));
    }
    const int N3 = Dm * Dm / 4;
    const float* Ws[4] = {Wq, Wk, Wv, Wo};
    for (int w = 0; w < 4; w++) {
        uint2* wh = (uint2*)(g_Wh + w * Dm * Dm);
        for (int i = idx; i < N3; i += stride) {
            float4 v = ((const float4*)Ws[w])[i];
            wh[i] = make_uint2(f2h2(v.x, v.y), f2h2(v.z, v.w));
        }
    }
}

// ---------------------------------------------------------------------------
// FUSED projections (unchanged from R12)
// ---------------------------------------------------------------------------
__global__ __launch_bounds__(256, 2)
void gemm_proj_fused(const __half* __restrict__ KVh, const __half* __restrict__ Qih,
                     const __half* __restrict__ Wh,
                     const float* __restrict__ bq, const float* __restrict__ bk,
                     const float* __restrict__ bv,
                     __half* __restrict__ Kout, __half* __restrict__ Vt,
                     __half* __restrict__ Qout)
{
    const int z = blockIdx.z;
    const bool isq = (z == 8);
    if (isq && blockIdx.x >= (Bsz * Sq) / 128) return;

    const int b = z >> 1;
    const int isv = z & 1;
    const __half* A;
    const __half* Wm;
    const float* bias;
    if (isq) { A = Qih; Wm = Wh; bias = bq; }
    else {
        A    = KVh + (size_t)b * Dm * HWk;
        Wm   = Wh + (size_t)(isv ? 2 : 1) * Dm * Dm;
        bias = isv ? bv : bk;
    }

    __shared__ uint32_t As2[2][2560];
    __shared__ uint32_t Ws2[2][128 * KS2];

    const int bm = blockIdx.x * 128;
    const int bn = blockIdx.y * 128;
    const int tid  = threadIdx.x;
    const int warp = tid >> 5;
    const int lane = tid & 31;
    const int gid  = lane >> 2;
    const int tig  = lane & 3;
    const int wm = (warp >> 1) * 32;
    const int wn = (warp & 1) * 64;

    const uint32_t asb = cvta_s(&As2[0][0]);
    const uint32_t wsb = cvta_s(&Ws2[0][0]);

    const int brow = ((lane >> 4) & 1) * 8 + (lane & 7);
    const int bchk = ((lane >> 3) & 1) * 4;
    const uint32_t ws0 = wsb + ((wn + brow) * KS2 + bchk) * 4;
    const int at_row = (lane & 7) + ((lane >> 4) & 1) * 8;
    const int at_mo  = ((lane >> 3) & 1) * 16;
    const int aq_row = (lane & 7) + ((lane >> 3) & 1) * 8;
    const int aq_co  = ((lane >> 4) & 1) * 16;

    float acc[2][8][4];
#pragma unroll
    for (int mf = 0; mf < 2; mf++)
#pragma unroll
        for (int nb = 0; nb < 8; nb++)
#pragma unroll
            for (int j = 0; j < 4; j++) acc[mf][nb][j] = 0.f;

    auto issueT = [&](int st, int k0) {
        const uint32_t stA = asb + st * 2560 * 4;
        const uint32_t stW = wsb + st * (128 * KS2 * 4);
        if (isq) {
            const uint32_t d = stA + (tid >> 1) * (AQW * 4) + (tid & 1) * 32;
            const __half* s = A + (size_t)(bm + (tid >> 1)) * Dm + k0 + (tid & 1) * 16;
            cp16(d, s); cp16(d + 16, s + 8);
        } else {
            const uint32_t d = stA + (tid >> 3) * (ATW * 4) + (tid & 7) * 32;
            const __half* s = A + (size_t)(k0 + (tid >> 3)) * HWk + bm + (tid & 7) * 16;
            cp16(d, s); cp16(d + 16, s + 8);
        }
        const uint32_t dw = stW + (tid >> 1) * (KS2 * 4) + (tid & 1) * 32;
        const __half* sw = Wm + (size_t)(bn + (tid >> 1)) * Dm + k0 + (tid & 1) * 16;
        cp16(dw, sw); cp16(dw + 16, sw + 8);
    };

    issueT(0, 0);
    cp_commit();
    cp_wait0();
    __syncthreads();

#pragma unroll
    for (int it = 0; it < 8; it++) {
        const int cur = it & 1;
        const bool more = (it + 1) < 8;
        if (more) { issueT(cur ^ 1, (it + 1) * 32); cp_commit(); }

        const uint32_t asc = asb + cur * 2560 * 4;
        const uint32_t wsc = ws0 + cur * (128 * KS2 * 4);
#pragma unroll
        for (int kb = 0; kb < 2; kb++) {
            uint32_t a[2][4];
            if (isq) {
#pragma unroll
                for (int mf = 0; mf < 2; mf++)
                    ldsm_x4(a[mf], asc + (wm + mf * 16 + aq_row) * (AQW * 4)
                                       + kb * 32 + aq_co);
            } else {
#pragma unroll
                for (int mf = 0; mf < 2; mf++)
                    ldsm_x4_t(a[mf], asc + (kb * 16 + at_row) * (ATW * 4)
                                         + (wm + mf * 16) * 2 + at_mo);
            }
#pragma unroll
            for (int p = 0; p < 4; p++) {
                uint32_t bf[4];
                ldsm_x4(bf, wsc + (p * 16 * KS2 + kb * 8) * 4);
                mma_f16(acc[0][2 * p    ], a[0], bf[0], bf[1]);
                mma_f16(acc[1][2 * p    ], a[1], bf[0], bf[1]);
                mma_f16(acc[0][2 * p + 1], a[0], bf[2], bf[3]);
                mma_f16(acc[1][2 * p + 1], a[1], bf[2], bf[3]);
            }
        }

        cp_wait0();
        __syncthreads();
    }

    if (isq) {
        const float scl = 0.17677669529663687f * 1.4426950408889634f;
#pragma unroll
        for (int mf = 0; mf < 2; mf++) {
            const int row = bm + wm + mf * 16 + gid;
#pragma unroll
            for (int nb = 0; nb < 8; nb++) {
                const int col = bn + wn + nb * 8 + 2 * tig;
                const float b0 = bias[col], b1 = bias[col + 1];
                *(uint32_t*)(Qout + (size_t)row * Dm + col) =
                    f2h2((acc[mf][nb][0] + b0) * scl, (acc[mf][nb][1] + b1) * scl);
                *(uint32_t*)(Qout + (size_t)(row + 8) * Dm + col) =
                    f2h2((acc[mf][nb][2] + b0) * scl, (acc[mf][nb][3] + b1) * scl);
            }
        }
    } else if (!isv) {
        __half* C = Kout + (size_t)b * HWk * Dm;
#pragma unroll
        for (int mf = 0; mf < 2; mf++) {
            const int row = bm + wm + mf * 16 + gid;
#pragma unroll
            for (int nb = 0; nb < 8; nb++) {
                const int col = bn + wn + nb * 8 + 2 * tig;
                const float b0 = bias[col], b1 = bias[col + 1];
                *(uint32_t*)(C + (size_t)row * Dm + col) =
                    f2h2(acc[mf][nb][0] + b0, acc[mf][nb][1] + b1);
                *(uint32_t*)(C + (size_t)(row + 8) * Dm + col) =
                    f2h2(acc[mf][nb][2] + b0, acc[mf][nb][3] + b1);
            }
        }
    } else {
        __half* C = Vt + (size_t)b * Dm * HWk;
#pragma unroll
        for (int mf = 0; mf < 2; mf++) {
            const int row = bm + wm + mf * 16 + gid;
#pragma unroll
            for (int nb = 0; nb < 8; nb++) {
                const int col = bn + wn + nb * 8 + 2 * tig;
                const float b0 = bias[col], b1 = bias[col + 1];
                C[(size_t)col       * HWk + row]     = __float2half_rn(acc[mf][nb][0] + b0);
                C[(size_t)(col + 1) * HWk + row]     = __float2half_rn(acc[mf][nb][1] + b1);
                C[(size_t)col       * HWk + row + 8] = __float2half_rn(acc[mf][nb][2] + b0);
                C[(size_t)(col + 1) * HWk + row + 8] = __float2half_rn(acc[mf][nb][3] + b1);
            }
        }
    }
}

// ---------------------------------------------------------------------------
// combine: 4-way split-softmax merge -> Ah (half, B*S x 256)
// thread handles 8 dims of one row.
// ---------------------------------------------------------------------------
__global__ __launch_bounds__(256)
void attn_combine(const float* __restrict__ Po, const float* __restrict__ Pm,
                  const float* __restrict__ Pl, __half* __restrict__ Ah)
{
    const int t = blockIdx.x * 256 + threadIdx.x;   // 2048*32 threads
    const int row = t >> 5;             // 0..2047
    const int dc  = (t & 31) * 8;       // dim offset 0..248
    const int b = row >> 9;
    const int q = row & (Sq - 1);
    const int h = dc >> 5;
    const int dof = dc & 31;

    const size_t i0 = (size_t)((b * NH + h) * NSPLIT) * Sq + q;
    float mv[NSPLIT], lv[NSPLIT];
    float m = -1e30f;
#pragma unroll
    for (int s = 0; s < NSPLIT; s++) {
        mv[s] = Pm[i0 + (size_t)s * Sq];
        lv[s] = Pl[i0 + (size_t)s * Sq];
        m = fmaxf(m, mv[s]);
    }
    float denom = 0.f;
    float wc[NSPLIT];
#pragma unroll
    for (int s = 0; s < NSPLIT; s++) {
        wc[s] = ex2f(mv[s] - m);
        denom += lv[s] * wc[s];
    }
    const float inv = 1.f / denom;
#pragma unroll
    for (int s = 0; s < NSPLIT; s++) wc[s] *= inv;

    float av[8];
#pragma unroll
    for (int j = 0; j < 8; j++) av[j] = 0.f;
#pragma unroll
    for (int s = 0; s < NSPLIT; s++) {
        const float* p = Po + (i0 + (size_t)s * Sq) * HD + dof;
        float4 v0 = *(const float4*)(p);
        float4 v1 = *(const float4*)(p + 4);
        av[0] += v0.x * wc[s]; av[1] += v0.y * wc[s];
        av[2] += v0.z * wc[s]; av[3] += v0.w * wc[s];
        av[4] += v1.x * wc[s]; av[5] += v1.y * wc[s];
        av[6] += v1.z * wc[s]; av[7] += v1.w * wc[s];
    }
    uint4 u;
    u.x = f2h2(av[0], av[1]); u.y = f2h2(av[2], av[3]);
    u.z = f2h2(av[4], av[5]); u.w = f2h2(av[6], av[7]);
    *(uint4*)(Ah + (size_t)row * Dm + dc) = u;
}

// ---------------------------------------------------------------------------
// O projection: pure cp.async half GEMM. BM=32, BN=64, 128 threads (4 warps,
// 2m x 2n, warp tile 16x32). Grid (64, 4) = 256 CTAs.
// ---------------------------------------------------------------------------
__global__ __launch_bounds__(128)
void gemm_out_f16(const __half* __restrict__ Ah, const __half* __restrict__ Woh,
                  const float* __restrict__ bias, float* __restrict__ C)
{
    __shared__ uint32_t As2[2][32 * KS2];
    __shared__ uint32_t Ws2[2][64 * KS2];

    const int bm = blockIdx.x * 32;
    const int bn = blockIdx.y * 64;
    const int tid  = threadIdx.x;
    const int warp = tid >> 5;
    const int lane = tid & 31;
    const int gid  = lane >> 2;
    const int tig  = lane & 3;
    const int wm = (warp >> 1) * 16;
    const int wn = (warp & 1) * 32;

    const uint32_t asbase = cvta_s(&As2[0][0]);
    const uint32_t wsbase = cvta_s(&Ws2[0][0]);
    const int brow = ((lane >> 4) & 1) * 8 + (lane & 7);
    const int bchk = ((lane >> 3) & 1) * 4;
    const int arow = ((lane >> 3) & 1) * 8 + (lane & 7);
    const int achk = ((lane >> 4) & 1) * 4;
    const uint32_t as0 = asbase + ((wm + arow) * KS2 + achk) * 4;
    const uint32_t ws0 = wsbase + ((wn + brow) * KS2 + bchk) * 4;

    float acc[4][4];
#pragma unroll
    for (int nb = 0; nb < 4; nb++)
#pragma unroll
        for (int j = 0; j < 4; j++) acc[nb][j] = 0.f;

    auto issueT = [&](int st, int k0) {
        // A: 32 rows x 64B; thread: row=tid>>2, 16B at (tid&3)*16
        const uint32_t da = asbase + st * (32 * KS2 * 4) + (tid >> 2) * (KS2 * 4) + (tid & 3) * 16;
        const __half* sa = Ah + (size_t)(bm + (tid >> 2)) * Dm + k0 + (tid & 3) * 8;
        cp16(da, sa);
        // W: 64 rows x 64B; thread: row=tid>>1, 32B at (tid&1)*32
        const uint32_t dw = wsbase + st * (64 * KS2 * 4) + (tid >> 1) * (KS2 * 4) + (tid & 1) * 32;
        const __half* sw = Woh + (size_t)(bn + (tid >> 1)) * Dm + k0 + (tid & 1) * 16;
        cp16(dw, sw); cp16(dw + 16, sw + 8);
    };

    issueT(0, 0);
    cp_commit();
    cp_wait0();
    __syncthreads();

#pragma unroll
    for (int it = 0; it < 8; it++) {
        const int cur = it & 1;
        const bool more = (it + 1) < 8;
        if (more) { issueT(cur ^ 1, (it + 1) * 32); cp_commit(); }

        const uint32_t asc = as0 + cur * (32 * KS2 * 4);
        const uint32_t wsc = ws0 + cur * (64 * KS2 * 4);
#pragma unroll
        for (int kb = 0; kb < 2; kb++) {
            uint32_t a[4];
            ldsm_x4(a, asc + kb * 8 * 4);
#pragma unroll
            for (int p = 0; p < 2; p++) {
                uint32_t bf[4];
                ldsm_x4(bf, wsc + (p * 16 * KS2 + kb * 8) * 4);
                mma_f16(acc[2 * p    ], a, bf[0], bf[1]);
                mma_f16(acc[2 * p + 1], a, bf[2], bf[3]);
            }
        }

        cp_wait0();
        __syncthreads();
    }

    const int row = bm + wm + gid;
#pragma unroll
    for (int nb = 0; nb < 4; nb++) {
        const int col = bn + wn + nb * 8 + 2 * tig;
        const float b0 = bias[col], b1 = bias[col + 1];
        *(float2*)(C + (size_t)row * Dm + col) =
            make_float2(acc[nb][0] + b0, acc[nb][1] + b1);
        *(float2*)(C + (size_t)(row + 8) * Dm + col) =
            make_float2(acc[nb][2] + b0, acc[nb][3] + b1);
    }
}

// ---------------------------------------------------------------------------
// fp16 flash attention, split-KV x4 (unchanged from R12)
// ---------------------------------------------------------------------------
__global__ __launch_bounds__(128)
void attn_mma(const __half* __restrict__ Qh, const __half* __restrict__ K,
              const __half* __restrict__ Vt, float* __restrict__ Po,
              float* __restrict__ Pm, float* __restrict__ Pl)
{
    const int h  = blockIdx.y;
    const int bz = blockIdx.z;
    const int b  = bz >> 2;
    const int sp = bz & 3;
    const int q0 = blockIdx.x * 64;

    __shared__ uint32_t Ks2[2][64][KS2];
    __shared__ uint32_t Vs2[2][32][VS2];

    const int tid  = threadIdx.x;
    const int warp = tid >> 5;
    const int lane = tid & 31;
    const int gid  = lane >> 2;
    const int tig  = lane & 3;

    const int brow = ((lane >> 4) & 1) * 8 + (lane & 7);
    const int bchk = ((lane >> 3) & 1) * 4;
    const uint32_t ksbase = cvta_s(&Ks2[0][0][0]);
    const uint32_t vsbase = cvta_s(&Vs2[0][0][0]);
    const uint32_t ks0 = ksbase + (brow * KS2 + bchk) * 4;
    const uint32_t vs0 = vsbase + (brow * VS2 + bchk) * 4;

    uint32_t qa[2][4];
    {
        const __half* Qb = Qh + ((size_t)(b * Sq + q0 + warp * 16)) * Dm + h * HD;
#pragma unroll
        for (int kb = 0; kb < 2; kb++) {
            const int d0 = kb * 16 + 2 * tig;
            qa[kb][0] = *(const uint32_t*)(Qb + (size_t)gid       * Dm + d0);
            qa[kb][1] = *(const uint32_t*)(Qb + (size_t)(gid + 8) * Dm + d0);
            qa[kb][2] = *(const uint32_t*)(Qb + (size_t)gid       * Dm + d0 + 8);
            qa[kb][3] = *(const uint32_t*)(Qb + (size_t)(gid + 8) * Dm + d0 + 8);
        }
    }

    float m_lo = -1e30f, m_hi = -1e30f;
    float l_lo = 0.f,    l_hi = 0.f;
    float o[4][4];
#pragma unroll
    for (int nb = 0; nb < 4; nb++)
#pragma unroll
        for (int i = 0; i < 4; i++) o[nb][i] = 0.f;

    const __half* Kb = K  + (size_t)b * HWk * Dm + h * HD;
    const __half* Vb = Vt + ((size_t)b * Dm + h * HD) * HWk;

    const int jbeg = sp * (HWk / NSPLIT);
    const int jend = jbeg + (HWk / NSPLIT);

    auto issueKV = [&](int st, int j0) {
        const uint32_t dk = ksbase + st * (64 * KS2 * 4) + (tid >> 1) * (KS2 * 4) + (tid & 1) * 32;
        const __half* sk = Kb + (size_t)(j0 + (tid >> 1)) * Dm + (tid & 1) * 16;
        cp16(dk, sk); cp16(dk + 16, sk + 8);
        const uint32_t dv = vsbase + st * (32 * VS2 * 4) + (tid >> 2) * (VS2 * 4) + (tid & 3) * 32;
        const __half* sv = Vb + (size_t)(tid >> 2) * HWk + j0 + (tid & 3) * 16;
        cp16(dv, sv); cp16(dv + 16, sv + 8);
    };

    issueKV(0, jbeg);
    cp_commit();
    cp_wait0();
    __syncthreads();

    int stage = 0;
    for (int j0 = jbeg; j0 < jend; j0 += 64) {
        const bool more = (j0 + 64) < jend;
        if (more) { issueKV(stage ^ 1, j0 + 64); cp_commit(); }

        float s[8][4];
#pragma unroll
        for (int nb = 0; nb < 8; nb++)
#pragma unroll
            for (int i = 0; i < 4; i++) s[nb][i] = 0.f;

        const uint32_t ksb = ks0 + stage * (64 * KS2 * 4);
#pragma unroll
        for (int kb = 0; kb < 2; kb++) {
#pragma unroll
            for (int p = 0; p < 4; p++) {
                uint32_t bf[4];
                ldsm_x4(bf, ksb + (p * 16 * KS2 + kb * 8) * 4);
                mma_f16(s[2 * p    ], qa[kb], bf[0], bf[1]);
                mma_f16(s[2 * p + 1], qa[kb], bf[2], bf[3]);
            }
        }

        float tmax_lo = -1e30f, tmax_hi = -1e30f;
#pragma unroll
        for (int nb = 0; nb < 8; nb++) {
            tmax_lo = fmaxf(tmax_lo, fmaxf(s[nb][0], s[nb][1]));
            tmax_hi = fmaxf(tmax_hi, fmaxf(s[nb][2], s[nb][3]));
        }
        tmax_lo = fmaxf(tmax_lo, __shfl_xor_sync(0xffffffffu, tmax_lo, 1));
        tmax_lo = fmaxf(tmax_lo, __shfl_xor_sync(0xffffffffu, tmax_lo, 2));
        tmax_hi = fmaxf(tmax_hi, __shfl_xor_sync(0xffffffffu, tmax_hi, 1));
        tmax_hi = fmaxf(tmax_hi, __shfl_xor_sync(0xffffffffu, tmax_hi, 2));

        const float mn_lo = fmaxf(m_lo, tmax_lo);
        const float mn_hi = fmaxf(m_hi, tmax_hi);
        const float al_lo = ex2f(m_lo - mn_lo);
        const float al_hi = ex2f(m_hi - mn_hi);
        m_lo = mn_lo; m_hi = mn_hi;
        l_lo *= al_lo; l_hi *= al_hi;
#pragma unroll
        for (int nb = 0; nb < 4; nb++) {
            o[nb][0] *= al_lo; o[nb][1] *= al_lo;
            o[nb][2] *= al_hi; o[nb][3] *= al_hi;
        }

        const uint32_t vsb = vs0 + stage * (32 * VS2 * 4);
#pragma unroll
        for (int kb = 0; kb < 4; kb++) {
            const float p0 = ex2f(s[2 * kb    ][0] - mn_lo);
            const float p1 = ex2f(s[2 * kb    ][1] - mn_lo);
            const float p2 = ex2f(s[2 * kb    ][2] - mn_hi);
            const float p3 = ex2f(s[2 * kb    ][3] - mn_hi);
            const float r0 = ex2f(s[2 * kb + 1][0] - mn_lo);
            const float r1 = ex2f(s[2 * kb + 1][1] - mn_lo);
            const float r2 = ex2f(s[2 * kb + 1][2] - mn_hi);
            const float r3 = ex2f(s[2 * kb + 1][3] - mn_hi);
            l_lo += p0 + p1 + r0 + r1;
            l_hi += p2 + p3 + r2 + r3;
            uint32_t pa[4];
            pa[0] = f2h2(p0, p1);
            pa[1] = f2h2(p2, p3);
            pa[2] = f2h2(r0, r1);
            pa[3] = f2h2(r2, r3);
#pragma unroll
            for (int p = 0; p < 2; p++) {
                uint32_t bf[4];
                ldsm_x4(bf, vsb + (p * 16 * VS2 + kb * 8) * 4);
                mma_f16(o[2 * p    ], pa, bf[0], bf[1]);
                mma_f16(o[2 * p + 1], pa, bf[2], bf[3]);
            }
        }

        cp_wait0();
        __syncthreads();
        stage ^= 1;
    }

    l_lo += __shfl_xor_sync(0xffffffffu, l_lo, 1);
    l_lo += __shfl_xor_sync(0xffffffffu, l_lo, 2);
    l_hi += __shfl_xor_sync(0xffffffffu, l_hi, 1);
    l_hi += __shfl_xor_sync(0xffffffffu, l_hi, 2);

    const int row0 = (((b * NH + h) * NSPLIT) + sp) * Sq + q0 + warp * 16;
#pragma unroll
    for (int nb = 0; nb < 4; nb++) {
        *(float2*)(Po + (size_t)(row0 + gid)     * HD + nb * 8 + 2 * tig) =
            make_float2(o[nb][0], o[nb][1]);
        *(float2*)(Po + (size_t)(row0 + gid + 8) * HD + nb * 8 + 2 * tig) =
            make_float2(o[nb][2], o[nb][3]);
    }
    if (tig == 0) {
        Pm[row0 + gid]     = m_lo;  Pl[row0 + gid]     = l_lo;
        Pm[row0 + gid + 8] = m_hi;  Pl[row0 + gid + 8] = l_hi;
    }
}

// ---------------------------------------------------------------------------
// Launch
// ---------------------------------------------------------------------------
extern "C" void kernel_launch(void* const* d_in, const int* in_sizes, int n_in,
                              void* d_out, int out_size)
{
    const float* query = (const float*)d_in[0];
    const float* keyv  = (const float*)d_in[1];
    const float* Wq    = (const float*)d_in[2];
    const float* bq    = (const float*)d_in[3];
    const float* Wk    = (const float*)d_in[4];
    const float* bk    = (const float*)d_in[5];
    const float* Wv    = (const float*)d_in[6];
    const float* bv    = (const float*)d_in[7];
    const float* Wo    = (const float*)d_in[8];
    const float* bo    = (const float*)d_in[9];
    float* out = (float*)d_out;

    __half *dKVh, *dQih, *dWh, *dQh, *dK, *dVt, *dAh;
    float *dPo, *dPm, *dPl;
    cudaGetSymbolAddress((void**)&dKVh, g_KVh);
    cudaGetSymbolAddress((void**)&dQih, g_Qih);
    cudaGetSymbolAddress((void**)&dWh,  g_Wh);
    cudaGetSymbolAddress((void**)&dQh,  g_Qh);
    cudaGetSymbolAddress((void**)&dK,   g_K);
    cudaGetSymbolAddress((void**)&dVt,  g_Vt);
    cudaGetSymbolAddress((void**)&dAh,  g_Ah);
    cudaGetSymbolAddress((void**)&dPo,  g_Po);
    cudaGetSymbolAddress((void**)&dPm,  g_Pm);
    cudaGetSymbolAddress((void**)&dPl,  g_Pl);

    prep_half<<<1024, 256>>>(keyv, query, Wq, Wk, Wv, Wo);
    {
        dim3 grid(HWk / 128, Dm / 128, Bsz * 2 + 1);
        gemm_proj_fused<<<grid, 256>>>(dKVh, dQih, dWh, bq, bk, bv, dK, dVt, dQh);
    }
    {
        dim3 grid(Sq / 64, NH, Bsz * NSPLIT);
        attn_mma<<<grid, 128>>>(dQh, dK, dVt, dPo, dPm, dPl);
    }
    attn_combine<<<(Bsz * Sq * 32) / 256, 256>>>(dPo, dPm, dPl, dAh);
    {
        dim3 grid((Bsz * Sq) / 32, Dm / 64);
        gemm_out_f16<<<grid, 128>>>(dAh, dWh + 3 * Dm * Dm, bo, out);
    }
}

// round 16
// speedup vs baseline: 1.4843x; 1.4843x over previous
#include <cuda_runtime.h>
#include <cuda_fp16.h>
#include <cstdint>

// Problem dims (fixed)
#define Dm   256
#define Bsz  4
#define Sq   512
#define HWk  4096
#define NH   8
#define HD   32
#define NSPLIT 4

// Scratch (no cudaMalloc allowed)
__device__ __half g_KVh[Bsz * Dm * HWk];          // kv half [b][k][m]
__device__ __half g_Qih[Bsz * Sq * Dm];           // query half
__device__ __half g_Wh[4 * Dm * Dm];              // Wq,Wk,Wv,Wo half
__device__ __half g_Qh[Bsz * Sq * Dm];            // projected Q (half, pre-scaled)
__device__ __half g_K [Bsz * HWk * Dm];           // projected K [b][hw][d]
__device__ __half g_Vt[Bsz * Dm * HWk];           // projected V transposed [b][d][hw]
__device__ float  g_Po[Bsz * NH * NSPLIT * Sq * HD];
__device__ float  g_Pm[Bsz * NH * NSPLIT * Sq];
__device__ float  g_Pl[Bsz * NH * NSPLIT * Sq];

__device__ __forceinline__ uint32_t f2h2(float x, float y) {
    __half2 h = __floats2half2_rn(x, y);
    return *reinterpret_cast<uint32_t*>(&h);
}
__device__ __forceinline__ float ex2f(float x) {
    float r;
    asm("ex2.approx.f32 %0, %1;" : "=f"(r) : "f"(x));
    return r;
}
__device__ __forceinline__ void mma_f16(float c[4], const uint32_t a[4],
                                        uint32_t b0, uint32_t b1) {
    asm volatile(
        "mma.sync.aligned.m16n8k16.row.col.f32.f16.f16.f32 "
        "{%0,%1,%2,%3}, {%4,%5,%6,%7}, {%8,%9}, {%0,%1,%2,%3};"
        : "+f"(c[0]), "+f"(c[1]), "+f"(c[2]), "+f"(c[3])
        : "r"(a[0]), "r"(a[1]), "r"(a[2]), "r"(a[3]), "r"(b0), "r"(b1));
}
__device__ __forceinline__ void ldsm_x4(uint32_t r[4], uint32_t addr) {
    asm volatile(
        "ldmatrix.sync.aligned.m8n8.x4.shared.b16 {%0,%1,%2,%3}, [%4];"
        : "=r"(r[0]), "=r"(r[1]), "=r"(r[2]), "=r"(r[3]) : "r"(addr));
}
__device__ __forceinline__ void ldsm_x4_t(uint32_t r[4], uint32_t addr) {
    asm volatile(
        "ldmatrix.sync.aligned.m8n8.x4.trans.shared.b16 {%0,%1,%2,%3}, [%4];"
        : "=r"(r[0]), "=r"(r[1]), "=r"(r[2]), "=r"(r[3]) : "r"(addr));
}
__device__ __forceinline__ uint32_t cvta_s(const void* p) {
    return (uint32_t)__cvta_generic_to_shared(p);
}
__device__ __forceinline__ void cp16(uint32_t dst, const void* src) {
    asm volatile("cp.async.cg.shared.global [%0], [%1], 16;"
                 :: "r"(dst), "l"(src));
}
__device__ __forceinline__ void cp_commit() {
    asm volatile("cp.async.commit_group;");
}
__device__ __forceinline__ void cp_wait0() {
    asm volatile("cp.async.wait_group 0;");
}

#define KS2 20    // [row][k2] half2 tiles
#define ATW 68    // proj KV A tile [k][m]
#define AQW 20    // proj Q A tile [m][k2]
#define VS2 36    // attn V [d][key] tile

// ---------------------------------------------------------------------------
// prep: fp32 -> fp16 conversions
// ---------------------------------------------------------------------------
__global__ void prep_half(const float* __restrict__ kv,
                          const float* __restrict__ query,
                          const float* __restrict__ Wq, const float* __restrict__ Wk,
                          const float* __restrict__ Wv, const float* __restrict__ Wo)
{
    const int idx = blockIdx.x * blockDim.x + threadIdx.x;
    const int stride = gridDim.x * blockDim.x;

    const int N1 = Bsz * Dm * HWk / 4;
    uint2* kvh = (uint2*)g_KVh;
    for (int i = idx; i < N1; i += stride) {
        float4 v = ((const float4*)kv)[i];
        kvh[i] = make_uint2(f2h2(v.x, v.y), f2h2(v.z, v.w));
    }
    const int N2 = Bsz * Sq * Dm / 4;
    uint2* qh = (uint2*)g_Qih;
    for (int i = idx; i < N2; i += stride) {
        float4 v = ((const float4*)query)[i];
        qh[i] = make_uint2(f2h2(v.x, v.y), f2h2(v.z, v.w));
    }
    const int N3 = Dm * Dm / 4;
    const float* Ws[4] = {Wq, Wk, Wv, Wo};
    for (int w = 0; w < 4; w++) {
        uint2* wh = (uint2*)(g_Wh + w * Dm * Dm);
        for (int i = idx; i < N3; i += stride) {
            float4 v = ((const float4*)Ws[w])[i];
            wh[i] = make_uint2(f2h2(v.x, v.y), f2h2(v.z, v.w));
        }
    }
}

// ---------------------------------------------------------------------------
// FUSED projections (identical to the 80.4us R12 build)
// ---------------------------------------------------------------------------
__global__ __launch_bounds__(256, 2)
void gemm_proj_fused(const __half* __restrict__ KVh, const __half* __restrict__ Qih,
                     const __half* __restrict__ Wh,
                     const float* __restrict__ bq, const float* __restrict__ bk,
                     const float* __restrict__ bv,
                     __half* __restrict__ Kout, __half* __restrict__ Vt,
                     __half* __restrict__ Qout)
{
    const int z = blockIdx.z;
    const bool isq = (z == 8);
    if (isq && blockIdx.x >= (Bsz * Sq) / 128) return;

    const int b = z >> 1;
    const int isv = z & 1;
    const __half* A;
    const __half* Wm;
    const float* bias;
    if (isq) { A = Qih; Wm = Wh; bias = bq; }
    else {
        A    = KVh + (size_t)b * Dm * HWk;
        Wm   = Wh + (size_t)(isv ? 2 : 1) * Dm * Dm;
        bias = isv ? bv : bk;
    }

    __shared__ uint32_t As2[2][2560];
    __shared__ uint32_t Ws2[2][128 * KS2];

    const int bm = blockIdx.x * 128;
    const int bn = blockIdx.y * 128;
    const int tid  = threadIdx.x;
    const int warp = tid >> 5;
    const int lane = tid & 31;
    const int gid  = lane >> 2;
    const int tig  = lane & 3;
    const int wm = (warp >> 1) * 32;
    const int wn = (warp & 1) * 64;

    const uint32_t asb = cvta_s(&As2[0][0]);
    const uint32_t wsb = cvta_s(&Ws2[0][0]);

    const int brow = ((lane >> 4) & 1) * 8 + (lane & 7);
    const int bchk = ((lane >> 3) & 1) * 4;
    const uint32_t ws0 = wsb + ((wn + brow) * KS2 + bchk) * 4;
    const int at_row = (lane & 7) + ((lane >> 4) & 1) * 8;
    const int at_mo  = ((lane >> 3) & 1) * 16;
    const int aq_row = (lane & 7) + ((lane >> 3) & 1) * 8;
    const int aq_co  = ((lane >> 4) & 1) * 16;

    float acc[2][8][4];
#pragma unroll
    for (int mf = 0; mf < 2; mf++)
#pragma unroll
        for (int nb = 0; nb < 8; nb++)
#pragma unroll
            for (int j = 0; j < 4; j++) acc[mf][nb][j] = 0.f;

    auto issueT = [&](int st, int k0) {
        const uint32_t stA = asb + st * 2560 * 4;
        const uint32_t stW = wsb + st * (128 * KS2 * 4);
        if (isq) {
            const uint32_t d = stA + (tid >> 1) * (AQW * 4) + (tid & 1) * 32;
            const __half* s = A + (size_t)(bm + (tid >> 1)) * Dm + k0 + (tid & 1) * 16;
            cp16(d, s); cp16(d + 16, s + 8);
        } else {
            const uint32_t d = stA + (tid >> 3) * (ATW * 4) + (tid & 7) * 32;
            const __half* s = A + (size_t)(k0 + (tid >> 3)) * HWk + bm + (tid & 7) * 16;
            cp16(d, s); cp16(d + 16, s + 8);
        }
        const uint32_t dw = stW + (tid >> 1) * (KS2 * 4) + (tid & 1) * 32;
        const __half* sw = Wm + (size_t)(bn + (tid >> 1)) * Dm + k0 + (tid & 1) * 16;
        cp16(dw, sw); cp16(dw + 16, sw + 8);
    };

    issueT(0, 0);
    cp_commit();
    cp_wait0();
    __syncthreads();

#pragma unroll
    for (int it = 0; it < 8; it++) {
        const int cur = it & 1;
        const bool more = (it + 1) < 8;
        if (more) { issueT(cur ^ 1, (it + 1) * 32); cp_commit(); }

        const uint32_t asc = asb + cur * 2560 * 4;
        const uint32_t wsc = ws0 + cur * (128 * KS2 * 4);
#pragma unroll
        for (int kb = 0; kb < 2; kb++) {
            uint32_t a[2][4];
            if (isq) {
#pragma unroll
                for (int mf = 0; mf < 2; mf++)
                    ldsm_x4(a[mf], asc + (wm + mf * 16 + aq_row) * (AQW * 4)
                                       + kb * 32 + aq_co);
            } else {
#pragma unroll
                for (int mf = 0; mf < 2; mf++)
                    ldsm_x4_t(a[mf], asc + (kb * 16 + at_row) * (ATW * 4)
                                         + (wm + mf * 16) * 2 + at_mo);
            }
#pragma unroll
            for (int p = 0; p < 4; p++) {
                uint32_t bf[4];
                ldsm_x4(bf, wsc + (p * 16 * KS2 + kb * 8) * 4);
                mma_f16(acc[0][2 * p    ], a[0], bf[0], bf[1]);
                mma_f16(acc[1][2 * p    ], a[1], bf[0], bf[1]);
                mma_f16(acc[0][2 * p + 1], a[0], bf[2], bf[3]);
                mma_f16(acc[1][2 * p + 1], a[1], bf[2], bf[3]);
            }
        }

        cp_wait0();
        __syncthreads();
    }

    if (isq) {
        const float scl = 0.17677669529663687f * 1.4426950408889634f;
#pragma unroll
        for (int mf = 0; mf < 2; mf++) {
            const int row = bm + wm + mf * 16 + gid;
#pragma unroll
            for (int nb = 0; nb < 8; nb++) {
                const int col = bn + wn + nb * 8 + 2 * tig;
                const float b0 = bias[col], b1 = bias[col + 1];
                *(uint32_t*)(Qout + (size_t)row * Dm + col) =
                    f2h2((acc[mf][nb][0] + b0) * scl, (acc[mf][nb][1] + b1) * scl);
                *(uint32_t*)(Qout + (size_t)(row + 8) * Dm + col) =
                    f2h2((acc[mf][nb][2] + b0) * scl, (acc[mf][nb][3] + b1) * scl);
            }
        }
    } else if (!isv) {
        __half* C = Kout + (size_t)b * HWk * Dm;
#pragma unroll
        for (int mf = 0; mf < 2; mf++) {
            const int row = bm + wm + mf * 16 + gid;
#pragma unroll
            for (int nb = 0; nb < 8; nb++) {
                const int col = bn + wn + nb * 8 + 2 * tig;
                const float b0 = bias[col], b1 = bias[col + 1];
                *(uint32_t*)(C + (size_t)row * Dm + col) =
                    f2h2(acc[mf][nb][0] + b0, acc[mf][nb][1] + b1);
                *(uint32_t*)(C + (size_t)(row + 8) * Dm + col) =
                    f2h2(acc[mf][nb][2] + b0, acc[mf][nb][3] + b1);
            }
        }
    } else {
        __half* C = Vt + (size_t)b * Dm * HWk;
#pragma unroll
        for (int mf = 0; mf < 2; mf++) {
            const int row = bm + wm + mf * 16 + gid;
#pragma unroll
            for (int nb = 0; nb < 8; nb++) {
                const int col = bn + wn + nb * 8 + 2 * tig;
                const float b0 = bias[col], b1 = bias[col + 1];
                C[(size_t)col       * HWk + row]     = __float2half_rn(acc[mf][nb][0] + b0);
                C[(size_t)(col + 1) * HWk + row]     = __float2half_rn(acc[mf][nb][1] + b1);
                C[(size_t)col       * HWk + row + 8] = __float2half_rn(acc[mf][nb][2] + b0);
                C[(size_t)(col + 1) * HWk + row + 8] = __float2half_rn(acc[mf][nb][3] + b1);
            }
        }
    }
}

// ---------------------------------------------------------------------------
// O projection with FUSED 4-way combine. BM=32, BN=64, 128 threads
// (4 warps, 2m x 2n, warp tile 16x32), grid (64, 4) = 256 CTAs.
// A rows built on the fly from Po/Pm/Pl (single pass); W via cp.async.
// ---------------------------------------------------------------------------
__global__ __launch_bounds__(128)
void gemm_out_f16(const float* __restrict__ Po, const float* __restrict__ Pm,
                  const float* __restrict__ Pl, const __half* __restrict__ Woh,
                  const float* __restrict__ bias, float* __restrict__ C)
{
    __shared__ uint32_t As2[2][32 * KS2];
    __shared__ uint32_t Ws2[2][64 * KS2];

    const int bm = blockIdx.x * 32;
    const int bn = blockIdx.y * 64;
    const int tid  = threadIdx.x;
    const int warp = tid >> 5;
    const int lane = tid & 31;
    const int gid  = lane >> 2;
    const int tig  = lane & 3;
    const int wm = (warp >> 1) * 16;
    const int wn = (warp & 1) * 32;

    const uint32_t asbase = cvta_s(&As2[0][0]);
    const uint32_t wsbase = cvta_s(&Ws2[0][0]);
    const int brow = ((lane >> 4) & 1) * 8 + (lane & 7);
    const int bchk = ((lane >> 3) & 1) * 4;
    const int arow = ((lane >> 3) & 1) * 8 + (lane & 7);
    const int achk = ((lane >> 4) & 1) * 4;
    const uint32_t as0 = asbase + ((wm + arow) * KS2 + achk) * 4;
    const uint32_t ws0 = wsbase + ((wn + brow) * KS2 + bchk) * 4;

    float acc[4][4];
#pragma unroll
    for (int nb = 0; nb < 4; nb++)
#pragma unroll
        for (int j = 0; j < 4; j++) acc[nb][j] = 0.f;

    const int rr = tid >> 2;          // row within block 0..31
    const int kq = (tid & 3) * 8;     // k offset within 32-chunk

    const int rowg = bm + rr;
    const int b = rowg >> 9;
    const int q = rowg & (Sq - 1);

    float4 ps[NSPLIT][2];
    float wc[NSPLIT];

    auto cpW = [&](int st, int k0) {
        const uint32_t d = wsbase + st * (64 * KS2 * 4) + (tid >> 1) * (KS2 * 4) + (tid & 1) * 32;
        const __half* s = Woh + (size_t)(bn + (tid >> 1)) * Dm + k0 + (tid & 1) * 16;
        cp16(d, s); cp16(d + 16, s + 8);
    };
    auto loadA = [&](int k0) {
        const int h  = k0 >> 5;
        const int bh = b * NH + h;
        const size_t i0 = (size_t)(bh * NSPLIT) * Sq + q;
        float mv[NSPLIT], lv[NSPLIT];
        float m = -1e30f;
#pragma unroll
        for (int s = 0; s < NSPLIT; s++) {
            mv[s] = Pm[i0 + (size_t)s * Sq];
            lv[s] = Pl[i0 + (size_t)s * Sq];
            m = fmaxf(m, mv[s]);
        }
        float denom = 0.f;
#pragma unroll
        for (int s = 0; s < NSPLIT; s++) {
            wc[s] = ex2f(mv[s] - m);
            denom += lv[s] * wc[s];
        }
        const float inv = 1.f / denom;
#pragma unroll
        for (int s = 0; s < NSPLIT; s++) {
            wc[s] *= inv;
            ps[s][0] = *(const float4*)(Po + (i0 + (size_t)s * Sq) * HD + kq);
            ps[s][1] = *(const float4*)(Po + (i0 + (size_t)s * Sq) * HD + kq + 4);
        }
    };
    auto stsA = [&](int st) {
        float av[8];
#pragma unroll
        for (int j = 0; j < 8; j++) {
            float a = 0.f;
#pragma unroll
            for (int s = 0; s < NSPLIT; s++)
                a += ((const float*)&ps[s][0])[j] * wc[s];
            av[j] = a;
        }
        uint4 ua;
        ua.x = f2h2(av[0], av[1]); ua.y = f2h2(av[2], av[3]);
        ua.z = f2h2(av[4], av[5]); ua.w = f2h2(av[6], av[7]);
        *(uint4*)((uint32_t*)As2 + st * (32 * KS2) + rr * KS2 + (tid & 3) * 4) = ua;
    };

    cpW(0, 0);
    cp_commit();
    loadA(0);
    stsA(0);
    cp_wait0();
    __syncthreads();

#pragma unroll
    for (int it = 0; it < 8; it++) {
        const int cur = it & 1;
        const bool more = (it + 1) < 8;
        if (more) { cpW(cur ^ 1, (it + 1) * 32); cp_commit(); loadA((it + 1) * 32); }

        const uint32_t asc = as0 + cur * (32 * KS2 * 4);
        const uint32_t wsc = ws0 + cur * (64 * KS2 * 4);
#pragma unroll
        for (int kb = 0; kb < 2; kb++) {
            uint32_t a[4];
            ldsm_x4(a, asc + kb * 8 * 4);
#pragma unroll
            for (int p = 0; p < 2; p++) {
                uint32_t bf[4];
                ldsm_x4(bf, wsc + (p * 16 * KS2 + kb * 8) * 4);
                mma_f16(acc[2 * p    ], a, bf[0], bf[1]);
                mma_f16(acc[2 * p + 1], a, bf[2], bf[3]);
            }
        }

        if (more) stsA(cur ^ 1);
        cp_wait0();
        __syncthreads();
    }

    const int row = bm + wm + gid;
#pragma unroll
    for (int nb = 0; nb < 4; nb++) {
        const int col = bn + wn + nb * 8 + 2 * tig;
        const float b0 = bias[col], b1 = bias[col + 1];
        *(float2*)(C + (size_t)row * Dm + col) =
            make_float2(acc[nb][0] + b0, acc[nb][1] + b1);
        *(float2*)(C + (size_t)(row + 8) * Dm + col) =
            make_float2(acc[nb][2] + b0, acc[nb][3] + b1);
    }
}

// ---------------------------------------------------------------------------
// fp16 flash attention, split-KV x4 (identical to the 80.4us R12 build)
// ---------------------------------------------------------------------------
__global__ __launch_bounds__(128)
void attn_mma(const __half* __restrict__ Qh, const __half* __restrict__ K,
              const __half* __restrict__ Vt, float* __restrict__ Po,
              float* __restrict__ Pm, float* __restrict__ Pl)
{
    const int h  = blockIdx.y;
    const int bz = blockIdx.z;
    const int b  = bz >> 2;
    const int sp = bz & 3;
    const int q0 = blockIdx.x * 64;

    __shared__ uint32_t Ks2[2][64][KS2];
    __shared__ uint32_t Vs2[2][32][VS2];

    const int tid  = threadIdx.x;
    const int warp = tid >> 5;
    const int lane = tid & 31;
    const int gid  = lane >> 2;
    const int tig  = lane & 3;

    const int brow = ((lane >> 4) & 1) * 8 + (lane & 7);
    const int bchk = ((lane >> 3) & 1) * 4;
    const uint32_t ksbase = cvta_s(&Ks2[0][0][0]);
    const uint32_t vsbase = cvta_s(&Vs2[0][0][0]);
    const uint32_t ks0 = ksbase + (brow * KS2 + bchk) * 4;
    const uint32_t vs0 = vsbase + (brow * VS2 + bchk) * 4;

    uint32_t qa[2][4];
    {
        const __half* Qb = Qh + ((size_t)(b * Sq + q0 + warp * 16)) * Dm + h * HD;
#pragma unroll
        for (int kb = 0; kb < 2; kb++) {
            const int d0 = kb * 16 + 2 * tig;
            qa[kb][0] = *(const uint32_t*)(Qb + (size_t)gid       * Dm + d0);
            qa[kb][1] = *(const uint32_t*)(Qb + (size_t)(gid + 8) * Dm + d0);
            qa[kb][2] = *(const uint32_t*)(Qb + (size_t)gid       * Dm + d0 + 8);
            qa[kb][3] = *(const uint32_t*)(Qb + (size_t)(gid + 8) * Dm + d0 + 8);
        }
    }

    float m_lo = -1e30f, m_hi = -1e30f;
    float l_lo = 0.f,    l_hi = 0.f;
    float o[4][4];
#pragma unroll
    for (int nb = 0; nb < 4; nb++)
#pragma unroll
        for (int i = 0; i < 4; i++) o[nb][i] = 0.f;

    const __half* Kb = K  + (size_t)b * HWk * Dm + h * HD;
    const __half* Vb = Vt + ((size_t)b * Dm + h * HD) * HWk;

    const int jbeg = sp * (HWk / NSPLIT);
    const int jend = jbeg + (HWk / NSPLIT);

    auto issueKV = [&](int st, int j0) {
        const uint32_t dk = ksbase + st * (64 * KS2 * 4) + (tid >> 1) * (KS2 * 4) + (tid & 1) * 32;
        const __half* sk = Kb + (size_t)(j0 + (tid >> 1)) * Dm + (tid & 1) * 16;
        cp16(dk, sk); cp16(dk + 16, sk + 8);
        const uint32_t dv = vsbase + st * (32 * VS2 * 4) + (tid >> 2) * (VS2 * 4) + (tid & 3) * 32;
        const __half* sv = Vb + (size_t)(tid >> 2) * HWk + j0 + (tid & 3) * 16;
        cp16(dv, sv); cp16(dv + 16, sv + 8);
    };

    issueKV(0, jbeg);
    cp_commit();
    cp_wait0();
    __syncthreads();

    int stage = 0;
    for (int j0 = jbeg; j0 < jend; j0 += 64) {
        const bool more = (j0 + 64) < jend;
        if (more) { issueKV(stage ^ 1, j0 + 64); cp_commit(); }

        float s[8][4];
#pragma unroll
        for (int nb = 0; nb < 8; nb++)
#pragma unroll
            for (int i = 0; i < 4; i++) s[nb][i] = 0.f;

        const uint32_t ksb = ks0 + stage * (64 * KS2 * 4);
#pragma unroll
        for (int kb = 0; kb < 2; kb++) {
#pragma unroll
            for (int p = 0; p < 4; p++) {
                uint32_t bf[4];
                ldsm_x4(bf, ksb + (p * 16 * KS2 + kb * 8) * 4);
                mma_f16(s[2 * p    ], qa[kb], bf[0], bf[1]);
                mma_f16(s[2 * p + 1], qa[kb], bf[2], bf[3]);
            }
        }

        float tmax_lo = -1e30f, tmax_hi = -1e30f;
#pragma unroll
        for (int nb = 0; nb < 8; nb++) {
            tmax_lo = fmaxf(tmax_lo, fmaxf(s[nb][0], s[nb][1]));
            tmax_hi = fmaxf(tmax_hi, fmaxf(s[nb][2], s[nb][3]));
        }
        tmax_lo = fmaxf(tmax_lo, __shfl_xor_sync(0xffffffffu, tmax_lo, 1));
        tmax_lo = fmaxf(tmax_lo, __shfl_xor_sync(0xffffffffu, tmax_lo, 2));
        tmax_hi = fmaxf(tmax_hi, __shfl_xor_sync(0xffffffffu, tmax_hi, 1));
        tmax_hi = fmaxf(tmax_hi, __shfl_xor_sync(0xffffffffu, tmax_hi, 2));

        const float mn_lo = fmaxf(m_lo, tmax_lo);
        const float mn_hi = fmaxf(m_hi, tmax_hi);
        const float al_lo = ex2f(m_lo - mn_lo);
        const float al_hi = ex2f(m_hi - mn_hi);
        m_lo = mn_lo; m_hi = mn_hi;
        l_lo *= al_lo; l_hi *= al_hi;
#pragma unroll
        for (int nb = 0; nb < 4; nb++) {
            o[nb][0] *= al_lo; o[nb][1] *= al_lo;
            o[nb][2] *= al_hi; o[nb][3] *= al_hi;
        }

        const uint32_t vsb = vs0 + stage * (32 * VS2 * 4);
#pragma unroll
        for (int kb = 0; kb < 4; kb++) {
            const float p0 = ex2f(s[2 * kb    ][0] - mn_lo);
            const float p1 = ex2f(s[2 * kb    ][1] - mn_lo);
            const float p2 = ex2f(s[2 * kb    ][2] - mn_hi);
            const float p3 = ex2f(s[2 * kb    ][3] - mn_hi);
            const float r0 = ex2f(s[2 * kb + 1][0] - mn_lo);
            const float r1 = ex2f(s[2 * kb + 1][1] - mn_lo);
            const float r2 = ex2f(s[2 * kb + 1][2] - mn_hi);
            const float r3 = ex2f(s[2 * kb + 1][3] - mn_hi);
            l_lo += p0 + p1 + r0 + r1;
            l_hi += p2 + p3 + r2 + r3;
            uint32_t pa[4];
            pa[0] = f2h2(p0, p1);
            pa[1] = f2h2(p2, p3);
            pa[2] = f2h2(r0, r1);
            pa[3] = f2h2(r2, r3);
#pragma unroll
            for (int p = 0; p < 2; p++) {
                uint32_t bf[4];
                ldsm_x4(bf, vsb + (p * 16 * VS2 + kb * 8) * 4);
                mma_f16(o[2 * p    ], pa, bf[0], bf[1]);
                mma_f16(o[2 * p + 1], pa, bf[2], bf[3]);
            }
        }

        cp_wait0();
        __syncthreads();
        stage ^= 1;
    }

    l_lo += __shfl_xor_sync(0xffffffffu, l_lo, 1);
    l_lo += __shfl_xor_sync(0xffffffffu, l_lo, 2);
    l_hi += __shfl_xor_sync(0xffffffffu, l_hi, 1);
    l_hi += __shfl_xor_sync(0xffffffffu, l_hi, 2);

    const int row0 = (((b * NH + h) * NSPLIT) + sp) * Sq + q0 + warp * 16;
#pragma unroll
    for (int nb = 0; nb < 4; nb++) {
        *(float2*)(Po + (size_t)(row0 + gid)     * HD + nb * 8 + 2 * tig) =
            make_float2(o[nb][0], o[nb][1]);
        *(float2*)(Po + (size_t)(row0 + gid + 8) * HD + nb * 8 + 2 * tig) =
            make_float2(o[nb][2], o[nb][3]);
    }
    if (tig == 0) {
        Pm[row0 + gid]     = m_lo;  Pl[row0 + gid]     = l_lo;
        Pm[row0 + gid + 8] = m_hi;  Pl[row0 + gid + 8] = l_hi;
    }
}

// ---------------------------------------------------------------------------
// Launch
// ---------------------------------------------------------------------------
extern "C" void kernel_launch(void* const* d_in, const int* in_sizes, int n_in,
                              void* d_out, int out_size)
{
    const float* query = (const float*)d_in[0];
    const float* keyv  = (const float*)d_in[1];
    const float* Wq    = (const float*)d_in[2];
    const float* bq    = (const float*)d_in[3];
    const float* Wk    = (const float*)d_in[4];
    const float* bk    = (const float*)d_in[5];
    const float* Wv    = (const float*)d_in[6];
    const float* bv    = (const float*)d_in[7];
    const float* Wo    = (const float*)d_in[8];
    const float* bo    = (const float*)d_in[9];
    float* out = (float*)d_out;

    __half *dKVh, *dQih, *dWh, *dQh, *dK, *dVt;
    float *dPo, *dPm, *dPl;
    cudaGetSymbolAddress((void**)&dKVh, g_KVh);
    cudaGetSymbolAddress((void**)&dQih, g_Qih);
    cudaGetSymbolAddress((void**)&dWh,  g_Wh);
    cudaGetSymbolAddress((void**)&dQh,  g_Qh);
    cudaGetSymbolAddress((void**)&dK,   g_K);
    cudaGetSymbolAddress((void**)&dVt,  g_Vt);
    cudaGetSymbolAddress((void**)&dPo,  g_Po);
    cudaGetSymbolAddress((void**)&dPm,  g_Pm);
    cudaGetSymbolAddress((void**)&dPl,  g_Pl);

    prep_half<<<1024, 256>>>(keyv, query, Wq, Wk, Wv, Wo);
    {
        dim3 grid(HWk / 128, Dm / 128, Bsz * 2 + 1);
        gemm_proj_fused<<<grid, 256>>>(dKVh, dQih, dWh, bq, bk, bv, dK, dVt, dQh);
    }
    {
        dim3 grid(Sq / 64, NH, Bsz * NSPLIT);
        attn_mma<<<grid, 128>>>(dQh, dK, dVt, dPo, dPm, dPl);
    }
    {
        dim3 grid((Bsz * Sq) / 32, Dm / 64);
        gemm_out_f16<<<grid, 128>>>(dPo, dPm, dPl, dWh + 3 * Dm * Dm, bo, out);
    }
}

// round 17
// speedup vs baseline: 1.5163x; 1.0216x over previous
#include <cuda_runtime.h>
#include <cuda_fp16.h>
#include <cstdint>

// Problem dims (fixed)
#define Dm   256
#define Bsz  4
#define Sq   512
#define HWk  4096
#define NH   8
#define HD   32
#define NSPLIT 4

// Scratch (no cudaMalloc allowed)
__device__ __half g_KVh[Bsz * Dm * HWk];          // kv half [b][k][m]
__device__ __half g_Qih[Bsz * Sq * Dm];           // query half
__device__ __half g_Wh[4 * Dm * Dm];              // Wq,Wk,Wv,Wo half
__device__ __half g_Qh[Bsz * Sq * Dm];            // projected Q (half, pre-scaled)
__device__ __half g_K [Bsz * HWk * Dm];           // projected K [b][hw][d]
__device__ __half g_Vt[Bsz * Dm * HWk];           // projected V transposed [b][d][hw]
__device__ float  g_Po[Bsz * NH * NSPLIT * Sq * HD];
__device__ float  g_Pm[Bsz * NH * NSPLIT * Sq];
__device__ float  g_Pl[Bsz * NH * NSPLIT * Sq];

__device__ __forceinline__ uint32_t f2h2(float x, float y) {
    __half2 h = __floats2half2_rn(x, y);
    return *reinterpret_cast<uint32_t*>(&h);
}
__device__ __forceinline__ float ex2f(float x) {
    float r;
    asm("ex2.approx.f32 %0, %1;" : "=f"(r) : "f"(x));
    return r;
}
__device__ __forceinline__ void mma_f16(float c[4], const uint32_t a[4],
                                        uint32_t b0, uint32_t b1) {
    asm volatile(
        "mma.sync.aligned.m16n8k16.row.col.f32.f16.f16.f32 "
        "{%0,%1,%2,%3}, {%4,%5,%6,%7}, {%8,%9}, {%0,%1,%2,%3};"
        : "+f"(c[0]), "+f"(c[1]), "+f"(c[2]), "+f"(c[3])
        : "r"(a[0]), "r"(a[1]), "r"(a[2]), "r"(a[3]), "r"(b0), "r"(b1));
}
__device__ __forceinline__ void ldsm_x4(uint32_t r[4], uint32_t addr) {
    asm volatile(
        "ldmatrix.sync.aligned.m8n8.x4.shared.b16 {%0,%1,%2,%3}, [%4];"
        : "=r"(r[0]), "=r"(r[1]), "=r"(r[2]), "=r"(r[3]) : "r"(addr));
}
__device__ __forceinline__ void ldsm_x4_t(uint32_t r[4], uint32_t addr) {
    asm volatile(
        "ldmatrix.sync.aligned.m8n8.x4.trans.shared.b16 {%0,%1,%2,%3}, [%4];"
        : "=r"(r[0]), "=r"(r[1]), "=r"(r[2]), "=r"(r[3]) : "r"(addr));
}
__device__ __forceinline__ uint32_t cvta_s(const void* p) {
    return (uint32_t)__cvta_generic_to_shared(p);
}
__device__ __forceinline__ void cp16(uint32_t dst, const void* src) {
    asm volatile("cp.async.cg.shared.global [%0], [%1], 16;"
                 :: "r"(dst), "l"(src));
}
__device__ __forceinline__ void cp_commit() {
    asm volatile("cp.async.commit_group;");
}
__device__ __forceinline__ void cp_wait0() {
    asm volatile("cp.async.wait_group 0;");
}

#define KS2 20    // [row][k2] half2 tiles
#define ATW 68    // proj KV A tile [k][m]
#define AQW 20    // proj Q A tile [m][k2]
#define VS2 36    // attn V [d][key] tile

// ---------------------------------------------------------------------------
// prep: fp32 -> fp16 conversions
// ---------------------------------------------------------------------------
__global__ void prep_half(const float* __restrict__ kv,
                          const float* __restrict__ query,
                          const float* __restrict__ Wq, const float* __restrict__ Wk,
                          const float* __restrict__ Wv, const float* __restrict__ Wo)
{
    const int idx = blockIdx.x * blockDim.x + threadIdx.x;
    const int stride = gridDim.x * blockDim.x;

    const int N1 = Bsz * Dm * HWk / 4;
    uint2* kvh = (uint2*)g_KVh;
    for (int i = idx; i < N1; i += stride) {
        float4 v = ((const float4*)kv)[i];
        kvh[i] = make_uint2(f2h2(v.x, v.y), f2h2(v.z, v.w));
    }
    const int N2 = Bsz * Sq * Dm / 4;
    uint2* qh = (uint2*)g_Qih;
    for (int i = idx; i < N2; i += stride) {
        float4 v = ((const float4*)query)[i];
        qh[i] = make_uint2(f2h2(v.x, v.y), f2h2(v.z, v.w));
    }
    const int N3 = Dm * Dm / 4;
    const float* Ws[4] = {Wq, Wk, Wv, Wo};
    for (int w = 0; w < 4; w++) {
        uint2* wh = (uint2*)(g_Wh + w * Dm * Dm);
        for (int i = idx; i < N3; i += stride) {
            float4 v = ((const float4*)Ws[w])[i];
            wh[i] = make_uint2(f2h2(v.x, v.y), f2h2(v.z, v.w));
        }
    }
}

// ---------------------------------------------------------------------------
// FUSED projections (identical to the 80.4us build)
// ---------------------------------------------------------------------------
__global__ __launch_bounds__(256, 2)
void gemm_proj_fused(const __half* __restrict__ KVh, const __half* __restrict__ Qih,
                     const __half* __restrict__ Wh,
                     const float* __restrict__ bq, const float* __restrict__ bk,
                     const float* __restrict__ bv,
                     __half* __restrict__ Kout, __half* __restrict__ Vt,
                     __half* __restrict__ Qout)
{
    const int z = blockIdx.z;
    const bool isq = (z == 8);
    if (isq && blockIdx.x >= (Bsz * Sq) / 128) return;

    const int b = z >> 1;
    const int isv = z & 1;
    const __half* A;
    const __half* Wm;
    const float* bias;
    if (isq) { A = Qih; Wm = Wh; bias = bq; }
    else {
        A    = KVh + (size_t)b * Dm * HWk;
        Wm   = Wh + (size_t)(isv ? 2 : 1) * Dm * Dm;
        bias = isv ? bv : bk;
    }

    __shared__ uint32_t As2[2][2560];
    __shared__ uint32_t Ws2[2][128 * KS2];

    const int bm = blockIdx.x * 128;
    const int bn = blockIdx.y * 128;
    const int tid  = threadIdx.x;
    const int warp = tid >> 5;
    const int lane = tid & 31;
    const int gid  = lane >> 2;
    const int tig  = lane & 3;
    const int wm = (warp >> 1) * 32;
    const int wn = (warp & 1) * 64;

    const uint32_t asb = cvta_s(&As2[0][0]);
    const uint32_t wsb = cvta_s(&Ws2[0][0]);

    const int brow = ((lane >> 4) & 1) * 8 + (lane & 7);
    const int bchk = ((lane >> 3) & 1) * 4;
    const uint32_t ws0 = wsb + ((wn + brow) * KS2 + bchk) * 4;
    const int at_row = (lane & 7) + ((lane >> 4) & 1) * 8;
    const int at_mo  = ((lane >> 3) & 1) * 16;
    const int aq_row = (lane & 7) + ((lane >> 3) & 1) * 8;
    const int aq_co  = ((lane >> 4) & 1) * 16;

    float acc[2][8][4];
#pragma unroll
    for (int mf = 0; mf < 2; mf++)
#pragma unroll
        for (int nb = 0; nb < 8; nb++)
#pragma unroll
            for (int j = 0; j < 4; j++) acc[mf][nb][j] = 0.f;

    auto issueT = [&](int st, int k0) {
        const uint32_t stA = asb + st * 2560 * 4;
        const uint32_t stW = wsb + st * (128 * KS2 * 4);
        if (isq) {
            const uint32_t d = stA + (tid >> 1) * (AQW * 4) + (tid & 1) * 32;
            const __half* s = A + (size_t)(bm + (tid >> 1)) * Dm + k0 + (tid & 1) * 16;
            cp16(d, s); cp16(d + 16, s + 8);
        } else {
            const uint32_t d = stA + (tid >> 3) * (ATW * 4) + (tid & 7) * 32;
            const __half* s = A + (size_t)(k0 + (tid >> 3)) * HWk + bm + (tid & 7) * 16;
            cp16(d, s); cp16(d + 16, s + 8);
        }
        const uint32_t dw = stW + (tid >> 1) * (KS2 * 4) + (tid & 1) * 32;
        const __half* sw = Wm + (size_t)(bn + (tid >> 1)) * Dm + k0 + (tid & 1) * 16;
        cp16(dw, sw); cp16(dw + 16, sw + 8);
    };

    issueT(0, 0);
    cp_commit();
    cp_wait0();
    __syncthreads();

#pragma unroll
    for (int it = 0; it < 8; it++) {
        const int cur = it & 1;
        const bool more = (it + 1) < 8;
        if (more) { issueT(cur ^ 1, (it + 1) * 32); cp_commit(); }

        const uint32_t asc = asb + cur * 2560 * 4;
        const uint32_t wsc = ws0 + cur * (128 * KS2 * 4);
#pragma unroll
        for (int kb = 0; kb < 2; kb++) {
            uint32_t a[2][4];
            if (isq) {
#pragma unroll
                for (int mf = 0; mf < 2; mf++)
                    ldsm_x4(a[mf], asc + (wm + mf * 16 + aq_row) * (AQW * 4)
                                       + kb * 32 + aq_co);
            } else {
#pragma unroll
                for (int mf = 0; mf < 2; mf++)
                    ldsm_x4_t(a[mf], asc + (kb * 16 + at_row) * (ATW * 4)
                                         + (wm + mf * 16) * 2 + at_mo);
            }
#pragma unroll
            for (int p = 0; p < 4; p++) {
                uint32_t bf[4];
                ldsm_x4(bf, wsc + (p * 16 * KS2 + kb * 8) * 4);
                mma_f16(acc[0][2 * p    ], a[0], bf[0], bf[1]);
                mma_f16(acc[1][2 * p    ], a[1], bf[0], bf[1]);
                mma_f16(acc[0][2 * p + 1], a[0], bf[2], bf[3]);
                mma_f16(acc[1][2 * p + 1], a[1], bf[2], bf[3]);
            }
        }

        cp_wait0();
        __syncthreads();
    }

    if (isq) {
        const float scl = 0.17677669529663687f * 1.4426950408889634f;
#pragma unroll
        for (int mf = 0; mf < 2; mf++) {
            const int row = bm + wm + mf * 16 + gid;
#pragma unroll
            for (int nb = 0; nb < 8; nb++) {
                const int col = bn + wn + nb * 8 + 2 * tig;
                const float b0 = bias[col], b1 = bias[col + 1];
                *(uint32_t*)(Qout + (size_t)row * Dm + col) =
                    f2h2((acc[mf][nb][0] + b0) * scl, (acc[mf][nb][1] + b1) * scl);
                *(uint32_t*)(Qout + (size_t)(row + 8) * Dm + col) =
                    f2h2((acc[mf][nb][2] + b0) * scl, (acc[mf][nb][3] + b1) * scl);
            }
        }
    } else if (!isv) {
        __half* C = Kout + (size_t)b * HWk * Dm;
#pragma unroll
        for (int mf = 0; mf < 2; mf++) {
            const int row = bm + wm + mf * 16 + gid;
#pragma unroll
            for (int nb = 0; nb < 8; nb++) {
                const int col = bn + wn + nb * 8 + 2 * tig;
                const float b0 = bias[col], b1 = bias[col + 1];
                *(uint32_t*)(C + (size_t)row * Dm + col) =
                    f2h2(acc[mf][nb][0] + b0, acc[mf][nb][1] + b1);
                *(uint32_t*)(C + (size_t)(row + 8) * Dm + col) =
                    f2h2(acc[mf][nb][2] + b0, acc[mf][nb][3] + b1);
            }
        }
    } else {
        __half* C = Vt + (size_t)b * Dm * HWk;
#pragma unroll
        for (int mf = 0; mf < 2; mf++) {
            const int row = bm + wm + mf * 16 + gid;
#pragma unroll
            for (int nb = 0; nb < 8; nb++) {
                const int col = bn + wn + nb * 8 + 2 * tig;
                const float b0 = bias[col], b1 = bias[col + 1];
                C[(size_t)col       * HWk + row]     = __float2half_rn(acc[mf][nb][0] + b0);
                C[(size_t)(col + 1) * HWk + row]     = __float2half_rn(acc[mf][nb][1] + b1);
                C[(size_t)col       * HWk + row + 8] = __float2half_rn(acc[mf][nb][2] + b0);
                C[(size_t)(col + 1) * HWk + row + 8] = __float2half_rn(acc[mf][nb][3] + b1);
            }
        }
    }
}

// ---------------------------------------------------------------------------
// O projection with fused combine. Combine weights wc[row][head][split] are
// PRECOMPUTED into SMEM in a prologue (loop-invariant); the mainloop's A
// loader is pure Po float4 LDGs + FMA + STS (no exp/div on the critical path).
// BM=32, BN=64, 128 threads, grid (64, 4) = 256 CTAs.
// ---------------------------------------------------------------------------
__global__ __launch_bounds__(128)
void gemm_out_f16(const float* __restrict__ Po, const float* __restrict__ Pm,
                  const float* __restrict__ Pl, const __half* __restrict__ Woh,
                  const float* __restrict__ bias, float* __restrict__ C)
{
    __shared__ uint32_t As2[2][32 * KS2];
    __shared__ uint32_t Ws2[2][64 * KS2];
    __shared__ float WC[32][NH][NSPLIT];   // 4KB combine-weight table

    const int bm = blockIdx.x * 32;
    const int bn = blockIdx.y * 64;
    const int tid  = threadIdx.x;
    const int warp = tid >> 5;
    const int lane = tid & 31;
    const int gid  = lane >> 2;
    const int tig  = lane & 3;
    const int wm = (warp >> 1) * 16;
    const int wn = (warp & 1) * 32;

    const uint32_t asbase = cvta_s(&As2[0][0]);
    const uint32_t wsbase = cvta_s(&Ws2[0][0]);
    const int brow = ((lane >> 4) & 1) * 8 + (lane & 7);
    const int bchk = ((lane >> 3) & 1) * 4;
    const int arow = ((lane >> 3) & 1) * 8 + (lane & 7);
    const int achk = ((lane >> 4) & 1) * 4;
    const uint32_t as0 = asbase + ((wm + arow) * KS2 + achk) * 4;
    const uint32_t ws0 = wsbase + ((wn + brow) * KS2 + bchk) * 4;

    float acc[4][4];
#pragma unroll
    for (int nb = 0; nb < 4; nb++)
#pragma unroll
        for (int j = 0; j < 4; j++) acc[nb][j] = 0.f;

    const int rr = tid >> 2;          // row within block 0..31
    const int kq = (tid & 3) * 8;     // k offset within 32-chunk

    const int rowg = bm + rr;
    const int b = rowg >> 9;
    const int q = rowg & (Sq - 1);

    auto cpW = [&](int st, int k0) {
        const uint32_t d = wsbase + st * (64 * KS2 * 4) + (tid >> 1) * (KS2 * 4) + (tid & 1) * 32;
        const __half* s = Woh + (size_t)(bn + (tid >> 1)) * Dm + k0 + (tid & 1) * 16;
        cp16(d, s); cp16(d + 16, s + 8);
    };

    // Issue first W tile, then compute the combine-weight table while it lands.
    cpW(0, 0);
    cp_commit();

    // Prologue: wc for 32 rows x 8 heads x 4 splits (2 tasks per thread)
#pragma unroll
    for (int t = tid; t < 32 * NH; t += 128) {
        const int r = t >> 3;          // row in block
        const int h = t & 7;           // head
        const int rg = bm + r;
        const int bb = rg >> 9;
        const int qq = rg & (Sq - 1);
        const size_t i0 = (size_t)((bb * NH + h) * NSPLIT) * Sq + qq;
        float mv[NSPLIT], lv[NSPLIT];
        float m = -1e30f;
#pragma unroll
        for (int s = 0; s < NSPLIT; s++) {
            mv[s] = Pm[i0 + (size_t)s * Sq];
            lv[s] = Pl[i0 + (size_t)s * Sq];
            m = fmaxf(m, mv[s]);
        }
        float denom = 0.f;
        float w[NSPLIT];
#pragma unroll
        for (int s = 0; s < NSPLIT; s++) {
            w[s] = ex2f(mv[s] - m);
            denom += lv[s] * w[s];
        }
        const float inv = 1.f / denom;
#pragma unroll
        for (int s = 0; s < NSPLIT; s++)
            WC[r][h][s] = w[s] * inv;
    }

    float4 ps[NSPLIT][2];

    auto loadA = [&](int k0) {
        const int h = k0 >> 5;
        const size_t i0 = (size_t)((b * NH + h) * NSPLIT) * Sq + q;
#pragma unroll
        for (int s = 0; s < NSPLIT; s++) {
            ps[s][0] = *(const float4*)(Po + (i0 + (size_t)s * Sq) * HD + kq);
            ps[s][1] = *(const float4*)(Po + (i0 + (size_t)s * Sq) * HD + kq + 4);
        }
    };
    auto stsA = [&](int st, int h) {
        float w0 = WC[rr][h][0], w1 = WC[rr][h][1];
        float w2 = WC[rr][h][2], w3 = WC[rr][h][3];
        float av[8];
#pragma unroll
        for (int j = 0; j < 8; j++) {
            av[j] = ((const float*)&ps[0][0])[j] * w0
                  + ((const float*)&ps[1][0])[j] * w1
                  + ((const float*)&ps[2][0])[j] * w2
                  + ((const float*)&ps[3][0])[j] * w3;
        }
        uint4 ua;
        ua.x = f2h2(av[0], av[1]); ua.y = f2h2(av[2], av[3]);
        ua.z = f2h2(av[4], av[5]); ua.w = f2h2(av[6], av[7]);
        *(uint4*)((uint32_t*)As2 + st * (32 * KS2) + rr * KS2 + (tid & 3) * 4) = ua;
    };

    loadA(0);
    __syncthreads();       // WC table ready (also covers As2 write below vs readers)
    stsA(0, 0);
    cp_wait0();
    __syncthreads();

#pragma unroll
    for (int it = 0; it < 8; it++) {
        const int cur = it & 1;
        const bool more = (it + 1) < 8;
        if (more) { cpW(cur ^ 1, (it + 1) * 32); cp_commit(); loadA((it + 1) * 32); }

        const uint32_t asc = as0 + cur * (32 * KS2 * 4);
        const uint32_t wsc = ws0 + cur * (64 * KS2 * 4);
#pragma unroll
        for (int kb = 0; kb < 2; kb++) {
            uint32_t a[4];
            ldsm_x4(a, asc + kb * 8 * 4);
#pragma unroll
            for (int p = 0; p < 2; p++) {
                uint32_t bf[4];
                ldsm_x4(bf, wsc + (p * 16 * KS2 + kb * 8) * 4);
                mma_f16(acc[2 * p    ], a, bf[0], bf[1]);
                mma_f16(acc[2 * p + 1], a, bf[2], bf[3]);
            }
        }

        if (more) stsA(cur ^ 1, it + 1);
        cp_wait0();
        __syncthreads();
    }

    const int row = bm + wm + gid;
#pragma unroll
    for (int nb = 0; nb < 4; nb++) {
        const int col = bn + wn + nb * 8 + 2 * tig;
        const float b0 = bias[col], b1 = bias[col + 1];
        *(float2*)(C + (size_t)row * Dm + col) =
            make_float2(acc[nb][0] + b0, acc[nb][1] + b1);
        *(float2*)(C + (size_t)(row + 8) * Dm + col) =
            make_float2(acc[nb][2] + b0, acc[nb][3] + b1);
    }
}

// ---------------------------------------------------------------------------
// fp16 flash attention, split-KV x4 (identical to the 80.4us build)
// ---------------------------------------------------------------------------
__global__ __launch_bounds__(128)
void attn_mma(const __half* __restrict__ Qh, const __half* __restrict__ K,
              const __half* __restrict__ Vt, float* __restrict__ Po,
              float* __restrict__ Pm, float* __restrict__ Pl)
{
    const int h  = blockIdx.y;
    const int bz = blockIdx.z;
    const int b  = bz >> 2;
    const int sp = bz & 3;
    const int q0 = blockIdx.x * 64;

    __shared__ uint32_t Ks2[2][64][KS2];
    __shared__ uint32_t Vs2[2][32][VS2];

    const int tid  = threadIdx.x;
    const int warp = tid >> 5;
    const int lane = tid & 31;
    const int gid  = lane >> 2;
    const int tig  = lane & 3;

    const int brow = ((lane >> 4) & 1) * 8 + (lane & 7);
    const int bchk = ((lane >> 3) & 1) * 4;
    const uint32_t ksbase = cvta_s(&Ks2[0][0][0]);
    const uint32_t vsbase = cvta_s(&Vs2[0][0][0]);
    const uint32_t ks0 = ksbase + (brow * KS2 + bchk) * 4;
    const uint32_t vs0 = vsbase + (brow * VS2 + bchk) * 4;

    uint32_t qa[2][4];
    {
        const __half* Qb = Qh + ((size_t)(b * Sq + q0 + warp * 16)) * Dm + h * HD;
#pragma unroll
        for (int kb = 0; kb < 2; kb++) {
            const int d0 = kb * 16 + 2 * tig;
            qa[kb][0] = *(const uint32_t*)(Qb + (size_t)gid       * Dm + d0);
            qa[kb][1] = *(const uint32_t*)(Qb + (size_t)(gid + 8) * Dm + d0);
            qa[kb][2] = *(const uint32_t*)(Qb + (size_t)gid       * Dm + d0 + 8);
            qa[kb][3] = *(const uint32_t*)(Qb + (size_t)(gid + 8) * Dm + d0 + 8);
        }
    }

    float m_lo = -1e30f, m_hi = -1e30f;
    float l_lo = 0.f,    l_hi = 0.f;
    float o[4][4];
#pragma unroll
    for (int nb = 0; nb < 4; nb++)
#pragma unroll
        for (int i = 0; i < 4; i++) o[nb][i] = 0.f;

    const __half* Kb = K  + (size_t)b * HWk * Dm + h * HD;
    const __half* Vb = Vt + ((size_t)b * Dm + h * HD) * HWk;

    const int jbeg = sp * (HWk / NSPLIT);
    const int jend = jbeg + (HWk / NSPLIT);

    auto issueKV = [&](int st, int j0) {
        const uint32_t dk = ksbase + st * (64 * KS2 * 4) + (tid >> 1) * (KS2 * 4) + (tid & 1) * 32;
        const __half* sk = Kb + (size_t)(j0 + (tid >> 1)) * Dm + (tid & 1) * 16;
        cp16(dk, sk); cp16(dk + 16, sk + 8);
        const uint32_t dv = vsbase + st * (32 * VS2 * 4) + (tid >> 2) * (VS2 * 4) + (tid & 3) * 32;
        const __half* sv = Vb + (size_t)(tid >> 2) * HWk + j0 + (tid & 3) * 16;
        cp16(dv, sv); cp16(dv + 16, sv + 8);
    };

    issueKV(0, jbeg);
    cp_commit();
    cp_wait0();
    __syncthreads();

    int stage = 0;
    for (int j0 = jbeg; j0 < jend; j0 += 64) {
        const bool more = (j0 + 64) < jend;
        if (more) { issueKV(stage ^ 1, j0 + 64); cp_commit(); }

        float s[8][4];
#pragma unroll
        for (int nb = 0; nb < 8; nb++)
#pragma unroll
            for (int i = 0; i < 4; i++) s[nb][i] = 0.f;

        const uint32_t ksb = ks0 + stage * (64 * KS2 * 4);
#pragma unroll
        for (int kb = 0; kb < 2; kb++) {
#pragma unroll
            for (int p = 0; p < 4; p++) {
                uint32_t bf[4];
                ldsm_x4(bf, ksb + (p * 16 * KS2 + kb * 8) * 4);
                mma_f16(s[2 * p    ], qa[kb], bf[0], bf[1]);
                mma_f16(s[2 * p + 1], qa[kb], bf[2], bf[3]);
            }
        }

        float tmax_lo = -1e30f, tmax_hi = -1e30f;
#pragma unroll
        for (int nb = 0; nb < 8; nb++) {
            tmax_lo = fmaxf(tmax_lo, fmaxf(s[nb][0], s[nb][1]));
            tmax_hi = fmaxf(tmax_hi, fmaxf(s[nb][2], s[nb][3]));
        }
        tmax_lo = fmaxf(tmax_lo, __shfl_xor_sync(0xffffffffu, tmax_lo, 1));
        tmax_lo = fmaxf(tmax_lo, __shfl_xor_sync(0xffffffffu, tmax_lo, 2));
        tmax_hi = fmaxf(tmax_hi, __shfl_xor_sync(0xffffffffu, tmax_hi, 1));
        tmax_hi = fmaxf(tmax_hi, __shfl_xor_sync(0xffffffffu, tmax_hi, 2));

        const float mn_lo = fmaxf(m_lo, tmax_lo);
        const float mn_hi = fmaxf(m_hi, tmax_hi);
        const float al_lo = ex2f(m_lo - mn_lo);
        const float al_hi = ex2f(m_hi - mn_hi);
        m_lo = mn_lo; m_hi = mn_hi;
        l_lo *= al_lo; l_hi *= al_hi;
#pragma unroll
        for (int nb = 0; nb < 4; nb++) {
            o[nb][0] *= al_lo; o[nb][1] *= al_lo;
            o[nb][2] *= al_hi; o[nb][3] *= al_hi;
        }

        const uint32_t vsb = vs0 + stage * (32 * VS2 * 4);
#pragma unroll
        for (int kb = 0; kb < 4; kb++) {
            const float p0 = ex2f(s[2 * kb    ][0] - mn_lo);
            const float p1 = ex2f(s[2 * kb    ][1] - mn_lo);
            const float p2 = ex2f(s[2 * kb    ][2] - mn_hi);
            const float p3 = ex2f(s[2 * kb    ][3] - mn_hi);
            const float r0 = ex2f(s[2 * kb + 1][0] - mn_lo);
            const float r1 = ex2f(s[2 * kb + 1][1] - mn_lo);
            const float r2 = ex2f(s[2 * kb + 1][2] - mn_hi);
            const float r3 = ex2f(s[2 * kb + 1][3] - mn_hi);
            l_lo += p0 + p1 + r0 + r1;
            l_hi += p2 + p3 + r2 + r3;
            uint32_t pa[4];
            pa[0] = f2h2(p0, p1);
            pa[1] = f2h2(p2, p3);
            pa[2] = f2h2(r0, r1);
            pa[3] = f2h2(r2, r3);
#pragma unroll
            for (int p = 0; p < 2; p++) {
                uint32_t bf[4];
                ldsm_x4(bf, vsb + (p * 16 * VS2 + kb * 8) * 4);
                mma_f16(o[2 * p    ], pa, bf[0], bf[1]);
                mma_f16(o[2 * p + 1], pa, bf[2], bf[3]);
            }
        }

        cp_wait0();
        __syncthreads();
        stage ^= 1;
    }

    l_lo += __shfl_xor_sync(0xffffffffu, l_lo, 1);
    l_lo += __shfl_xor_sync(0xffffffffu, l_lo, 2);
    l_hi += __shfl_xor_sync(0xffffffffu, l_hi, 1);
    l_hi += __shfl_xor_sync(0xffffffffu, l_hi, 2);

    const int row0 = (((b * NH + h) * NSPLIT) + sp) * Sq + q0 + warp * 16;
#pragma unroll
    for (int nb = 0; nb < 4; nb++) {
        *(float2*)(Po + (size_t)(row0 + gid)     * HD + nb * 8 + 2 * tig) =
            make_float2(o[nb][0], o[nb][1]);
        *(float2*)(Po + (size_t)(row0 + gid + 8) * HD + nb * 8 + 2 * tig) =
            make_float2(o[nb][2], o[nb][3]);
    }
    if (tig == 0) {
        Pm[row0 + gid]     = m_lo;  Pl[row0 + gid]     = l_lo;
        Pm[row0 + gid + 8] = m_hi;  Pl[row0 + gid + 8] = l_hi;
    }
}

// ---------------------------------------------------------------------------
// Launch
// ---------------------------------------------------------------------------
extern "C" void kernel_launch(void* const* d_in, const int* in_sizes, int n_in,
                              void* d_out, int out_size)
{
    const float* query = (const float*)d_in[0];
    const float* keyv  = (const float*)d_in[1];
    const float* Wq    = (const float*)d_in[2];
    const float* bq    = (const float*)d_in[3];
    const float* Wk    = (const float*)d_in[4];
    const float* bk    = (const float*)d_in[5];
    const float* Wv    = (const float*)d_in[6];
    const float* bv    = (const float*)d_in[7];
    const float* Wo    = (const float*)d_in[8];
    const float* bo    = (const float*)d_in[9];
    float* out = (float*)d_out;

    __half *dKVh, *dQih, *dWh, *dQh, *dK, *dVt;
    float *dPo, *dPm, *dPl;
    cudaGetSymbolAddress((void**)&dKVh, g_KVh);
    cudaGetSymbolAddress((void**)&dQih, g_Qih);
    cudaGetSymbolAddress((void**)&dWh,  g_Wh);
    cudaGetSymbolAddress((void**)&dQh,  g_Qh);
    cudaGetSymbolAddress((void**)&dK,   g_K);
    cudaGetSymbolAddress((void**)&dVt,  g_Vt);
    cudaGetSymbolAddress((void**)&dPo,  g_Po);
    cudaGetSymbolAddress((void**)&dPm,  g_Pm);
    cudaGetSymbolAddress((void**)&dPl,  g_Pl);

    prep_half<<<1024, 256>>>(keyv, query, Wq, Wk, Wv, Wo);
    {
        dim3 grid(HWk / 128, Dm / 128, Bsz * 2 + 1);
        gemm_proj_fused<<<grid, 256>>>(dKVh, dQih, dWh, bq, bk, bv, dK, dVt, dQh);
    }
    {
        dim3 grid(Sq / 64, NH, Bsz * NSPLIT);
        attn_mma<<<grid, 128>>>(dQh, dK, dVt, dPo, dPm, dPl);
    }
    {
        dim3 grid((Bsz * Sq) / 32, Dm / 64);
        gemm_out_f16<<<grid, 128>>>(dPo, dPm, dPl, dWh + 3 * Dm * Dm, bo, out);
    }
}